// round 4
// baseline (speedup 1.0000x reference)
#include <cuda_runtime.h>
#include <math.h>

// ---------------- problem constants (fixed shapes) ----------------
#define B_      2
#define N_      6
#define CAMS    (B_ * N_)          // 12
#define CAM_C   256
#define OUT_C   64
#define D_BINS  59
#define M_FEAT  (D_BINS + OUT_C)   // 123
#define FH      16
#define FW      44
#define HW      (FH * FW)          // 704
#define NX      128
#define NY      128
#define NCELL   (NX * NY)          // 16384 (NZ = 1)

// GEMM tiling
#define BM 128          // padded from 123
#define BN 64           // pixels per block
#define BK 32
#define NTHREADS 256

#define WS_STRIDE 130
#define XS_STRIDE 68
#define DS_STRIDE 61
#define CS_STRIDE 68

#define REP 4                               // scratch replicas (atomic spread)
#define SCR_SZ (B_ * NCELL * OUT_C)         // floats per replica

typedef unsigned long long ull;

// replicated scratch BEV accumulator, channel-contiguous: [REP][B, cell, OUT_C].
// Zero-initialized at module load; transpose kernel re-zeroes after reading,
// so it is always zero at kernel_launch entry (graph replays included).
__device__ float g_scratch[REP * SCR_SZ];   // 32 MB

// ---------------- fused GEMM + softmax + scatter ----------------
__global__ __launch_bounds__(NTHREADS, 1)
void lss_fused_kernel(const float* __restrict__ x,
                      const float* __restrict__ rots,
                      const float* __restrict__ trans,
                      const float* __restrict__ intrins,
                      const float* __restrict__ depth_w,
                      const float* __restrict__ depth_b)
{
    __shared__ __align__(16) float smem[BN * DS_STRIDE + BN * CS_STRIDE];
    __shared__ float comb[9];
    __shared__ float tr[3];

    float* Ws = smem;                       // [kk][m], stride 130
    float* Xs = smem + BK * WS_STRIDE;      // [kk][np], stride 68

    const int cam = blockIdx.y;           // 0..11
    const int b   = cam / N_;
    const int p0  = blockIdx.x * BN;      // pixel tile start
    const int tid = threadIdx.x;
    const int tm  = tid >> 4;             // 0..15 -> 8 M-rows (4 even pairs)
    const int tn  = tid & 15;             // 0..15 -> 4 pixels

    // --- geometry setup: comb = rots @ inv(K) (thread 0) ---
    if (tid == 0) {
        const float* R = rots    + cam * 9;
        const float* K = intrins + cam * 9;
        float a = K[0], bb = K[1], c = K[2];
        float d = K[3], e  = K[4], f = K[5];
        float g = K[6], h  = K[7], i = K[8];
        float A  = e * i - f * h;
        float Bv = -(d * i - f * g);
        float Cv = d * h - e * g;
        float id = 1.0f / (a * A + bb * Bv + c * Cv);
        float inv[9];
        inv[0] = A * id;  inv[1] = (c * h - bb * i) * id; inv[2] = (bb * f - c * e) * id;
        inv[3] = Bv * id; inv[4] = (a * i - c * g) * id;  inv[5] = (c * d - a * f) * id;
        inv[6] = Cv * id; inv[7] = (bb * g - a * h) * id; inv[8] = (a * e - bb * d) * id;
        #pragma unroll
        for (int r = 0; r < 3; r++)
            #pragma unroll
            for (int col = 0; col < 3; col++)
                comb[r * 3 + col] = R[r * 3 + 0] * inv[0 + col]
                                  + R[r * 3 + 1] * inv[3 + col]
                                  + R[r * 3 + 2] * inv[6 + col];
        tr[0] = trans[cam * 3 + 0];
        tr[1] = trans[cam * 3 + 1];
        tr[2] = trans[cam * 3 + 2];
    }

    // --- phase 1: feat = W @ x, FFMA2 over M-pairs ---
    ull acc[4][4];
    #pragma unroll
    for (int i4 = 0; i4 < 4; i4++)
        #pragma unroll
        for (int j = 0; j < 4; j++) acc[i4][j] = 0ull;

    const float* xcam = x + (size_t)cam * CAM_C * HW;

    for (int kc = 0; kc < CAM_C; kc += BK) {
        #pragma unroll
        for (int idx = tid; idx < BM * BK; idx += NTHREADS) {
            int m  = idx >> 5;
            int kk = idx & 31;
            Ws[kk * WS_STRIDE + m] = (m < M_FEAT) ? depth_w[m * CAM_C + kc + kk] : 0.f;
        }
        #pragma unroll
        for (int idx = tid; idx < BK * BN; idx += NTHREADS) {
            int kk = idx >> 6;
            int np = idx & 63;
            Xs[kk * XS_STRIDE + np] = xcam[(size_t)(kc + kk) * HW + p0 + np];
        }
        __syncthreads();

        #pragma unroll 4
        for (int kk = 0; kk < BK; kk++) {
            ull wp[4];
            #pragma unroll
            for (int i4 = 0; i4 < 4; i4++)
                wp[i4] = *(const ull*)&Ws[kk * WS_STRIDE + tm * 8 + 2 * i4];
            ull xd[4];
            #pragma unroll
            for (int j = 0; j < 4; j++) {
                float xv = Xs[kk * XS_STRIDE + tn * 4 + j];
                asm("mov.b64 %0, {%1, %1};" : "=l"(xd[j]) : "f"(xv));
            }
            #pragma unroll
            for (int i4 = 0; i4 < 4; i4++)
                #pragma unroll
                for (int j = 0; j < 4; j++)
                    asm("fma.rn.f32x2 %0, %1, %2, %0;"
                        : "+l"(acc[i4][j]) : "l"(wp[i4]), "l"(xd[j]));
        }
        __syncthreads();
    }

    // --- phase 2: unpack accs (+bias) into depthS / ctxS ---
    float* depthS = smem;                     // [pix][61]
    float* ctxS   = smem + BN * DS_STRIDE;    // [pix][68]

    #pragma unroll
    for (int i4 = 0; i4 < 4; i4++) {
        int m0 = tm * 8 + 2 * i4;
        float b0 = (m0     < M_FEAT) ? depth_b[m0]     : 0.f;
        float b1 = (m0 + 1 < M_FEAT) ? depth_b[m0 + 1] : 0.f;
        #pragma unroll
        for (int j = 0; j < 4; j++) {
            float lo, hi;
            asm("mov.b64 {%0, %1}, %2;" : "=f"(lo), "=f"(hi) : "l"(acc[i4][j]));
            int pix = tn * 4 + j;
            float v0 = lo + b0, v1 = hi + b1;
            if (m0 < D_BINS)       depthS[pix * DS_STRIDE + m0] = v0;
            else if (m0 < M_FEAT)  ctxS[pix * CS_STRIDE + (m0 - D_BINS)] = v0;
            int m1 = m0 + 1;
            if (m1 < D_BINS)       depthS[pix * DS_STRIDE + m1] = v1;
            else if (m1 < M_FEAT)  ctxS[pix * CS_STRIDE + (m1 - D_BINS)] = v1;
        }
    }
    __syncthreads();

    // --- softmax over depth bins, one thread per pixel ---
    if (tid < BN) {
        float* row = depthS + tid * DS_STRIDE;
        float mx = -1e30f;
        #pragma unroll 4
        for (int d = 0; d < D_BINS; d++) mx = fmaxf(mx, row[d]);
        float s = 0.f;
        #pragma unroll 4
        for (int d = 0; d < D_BINS; d++) {
            float e = __expf(row[d] - mx);
            row[d] = e;
            s += e;
        }
        float invs = 1.0f / s;
        #pragma unroll 4
        for (int d = 0; d < D_BINS; d++) row[d] *= invs;
    }
    __syncthreads();

    // --- scatter: flat loop, replica-spread + channel-rotated red.v4 ---
    const float c00 = comb[0], c01 = comb[1], c02 = comb[2];
    const float c10 = comb[3], c11 = comb[4], c12 = comb[5];
    const float c20 = comb[6], c21 = comb[7], c22 = comb[8];
    const float t0 = tr[0], t1 = tr[1], t2 = tr[2];
    const float xstep = 703.0f / 43.0f;
    const float ystep = 255.0f / 15.0f;

    // replica: mix warp id and block ids so concurrent same-cell writers split
    const int rep = ((tid >> 5) + blockIdx.x + blockIdx.y) & (REP - 1);
    float* base = g_scratch + (size_t)rep * SCR_SZ + (size_t)b * NCELL * OUT_C;
    const int rot = tid & 15;   // de-convoy: start channel walk at different word

    for (int idx = tid; idx < BN * D_BINS; idx += NTHREADS) {
        int pix = idx / D_BINS;
        int d   = idx - pix * D_BINS;
        int hw  = p0 + pix;
        int h   = hw / FW;
        int w   = hw - h * FW;

        float ds  = 1.0f + (float)d;
        float xim = (float)w * xstep;
        float yim = (float)h * ystep;
        float px = xim * ds, py = yim * ds, pz = ds;

        float gx = c00 * px + c01 * py + c02 * pz + t0;
        float gy = c10 * px + c11 * py + c12 * pz + t1;
        float gz = c20 * px + c21 * py + c22 * pz + t2;

        int cx = (int)floorf((gx + 51.2f) / 0.8f);
        int cy = (int)floorf((gy + 51.2f) / 0.8f);
        int cz = (int)floorf((gz + 10.0f) / 20.0f);

        if (((unsigned)cx < (unsigned)NX) && ((unsigned)cy < (unsigned)NY) && cz == 0) {
            float dwgt = depthS[pix * DS_STRIDE + d];
            float* dst = base + ((size_t)cy * NX + cx) * OUT_C;
            const float* cvf = ctxS + pix * CS_STRIDE;
            #pragma unroll
            for (int k = 0; k < OUT_C / 4; k++) {
                int c4 = (k + rot) & 15;
                float4 v = *(const float4*)(cvf + c4 * 4);
                asm volatile(
                    "red.global.add.v4.f32 [%0], {%1, %2, %3, %4};"
                    :: "l"(dst + c4 * 4),
                       "f"(v.x * dwgt), "f"(v.y * dwgt), "f"(v.z * dwgt), "f"(v.w * dwgt)
                    : "memory");
            }
        }
    }
}

// ---- transpose (B, cell, C) -> (B, C, cell): sum replicas + self-clean ----
__global__ void transpose_bev_kernel(float* __restrict__ out)
{
    __shared__ float tile[32][33];
    int bz    = blockIdx.z;                 // batch
    int c0    = blockIdx.y * 32;            // channel tile
    int cell0 = blockIdx.x * 32;            // cell tile
    int tx = threadIdx.x, ty = threadIdx.y; // 32 x 8

    #pragma unroll
    for (int i = ty; i < 32; i += 8) {
        size_t off = ((size_t)bz * NCELL + cell0 + i) * OUT_C + c0 + tx;
        float v0 = g_scratch[0 * SCR_SZ + off];
        float v1 = g_scratch[1 * SCR_SZ + off];
        float v2 = g_scratch[2 * SCR_SZ + off];
        float v3 = g_scratch[3 * SCR_SZ + off];
        g_scratch[0 * SCR_SZ + off] = 0.f;   // restore zero for next replay
        g_scratch[1 * SCR_SZ + off] = 0.f;
        g_scratch[2 * SCR_SZ + off] = 0.f;
        g_scratch[3 * SCR_SZ + off] = 0.f;
        tile[i][tx] = (v0 + v1) + (v2 + v3);
    }
    __syncthreads();
    #pragma unroll
    for (int i = ty; i < 32; i += 8)
        out[((size_t)(bz * OUT_C + c0 + i)) * NCELL + cell0 + tx] = tile[tx][i];
}

// ---------------- launch ----------------
extern "C" void kernel_launch(void* const* d_in, const int* in_sizes, int n_in,
                              void* d_out, int out_size)
{
    const float* x       = (const float*)d_in[0];
    const float* rots    = (const float*)d_in[1];
    const float* trans   = (const float*)d_in[2];
    const float* intrins = (const float*)d_in[3];
    const float* depth_w = (const float*)d_in[4];
    const float* depth_b = (const float*)d_in[5];
    float* out = (float*)d_out;

    // fused GEMM + softmax + scatter: one block per (camera, 64-pixel tile)
    {
        dim3 grid(HW / BN, CAMS);   // (11, 12)
        lss_fused_kernel<<<grid, NTHREADS>>>(x, rots, trans, intrins, depth_w, depth_b);
    }

    // transpose (sums replicas) into output layout (B, OUT_C, NY, NX), re-zero
    {
        dim3 grid(NCELL / 32, OUT_C / 32, B_);   // (512, 2, 2)
        transpose_bev_kernel<<<grid, dim3(32, 8)>>>(out);
    }
    (void)in_sizes; (void)n_in; (void)out_size;
}

// round 5
// speedup vs baseline: 1.1306x; 1.1306x over previous
#include <cuda_runtime.h>
#include <math.h>

// ---------------- problem constants (fixed shapes) ----------------
#define B_      2
#define N_      6
#define CAMS    (B_ * N_)          // 12
#define CAM_C   256
#define OUT_C   64
#define D_BINS  59
#define M_FEAT  (D_BINS + OUT_C)   // 123
#define FH      16
#define FW      44
#define HW      (FH * FW)          // 704
#define NX      128
#define NY      128
#define NCELL   (NX * NY)          // 16384 (NZ = 1)

// GEMM tiling
#define BM 128          // padded from 123
#define BN 64           // pixels per block
#define BK 32
#define NTHREADS 512

#define WS_STRIDE 130   // even -> aligned LDS.64 rows
#define XS_STRIDE 68
#define DS_STRIDE 61    // depthS per-pixel row (odd -> conflict-free both phases)
#define CS_STRIDE 68    // ctxS per-pixel row (16B-multiple -> aligned float4)

#define SCR_SZ (B_ * NCELL * OUT_C)   // 2M floats = 8 MB

typedef unsigned long long ull;

// scratch BEV accumulator, channel-contiguous: (B, cell, OUT_C).
// Zeroed by zero_scratch_kernel at the head of every launch/replay.
__device__ float g_scratch[SCR_SZ];

// ---------------- zero scratch (runs BEFORE the reds, on clean lines) -------
__global__ void zero_scratch_kernel() {
    size_t i = (size_t)blockIdx.x * blockDim.x + threadIdx.x;
    ((float4*)g_scratch)[i] = make_float4(0.f, 0.f, 0.f, 0.f);
}

// ---------------- fused GEMM + softmax + scatter ----------------
__global__ __launch_bounds__(NTHREADS, 1)
void lss_fused_kernel(const float* __restrict__ x,
                      const float* __restrict__ rots,
                      const float* __restrict__ trans,
                      const float* __restrict__ intrins,
                      const float* __restrict__ depth_w,
                      const float* __restrict__ depth_b)
{
    // phase 1: Ws[32][130] + Xs[32][68] = 6336 floats
    // phase 2: depthS[64][61] + ctxS[64][68] = 8256 floats (33 KB)
    __shared__ __align__(16) float smem[BN * DS_STRIDE + BN * CS_STRIDE];
    __shared__ float comb[9];
    __shared__ float tr[3];

    float* Ws = smem;                       // [kk][m], stride 130
    float* Xs = smem + BK * WS_STRIDE;      // [kk][np], stride 68

    const int cam = blockIdx.y;           // 0..11
    const int b   = cam / N_;
    const int p0  = blockIdx.x * BN;      // pixel tile start
    const int tid = threadIdx.x;
    const int tm  = tid >> 5;             // 0..15 -> 8 M-rows (4 even pairs)
    const int tn  = tid & 31;             // 0..31 -> 2 pixels

    // --- geometry setup: comb = rots @ inv(K) (thread 0) ---
    if (tid == 0) {
        const float* R = rots    + cam * 9;
        const float* K = intrins + cam * 9;
        float a = K[0], bb = K[1], c = K[2];
        float d = K[3], e  = K[4], f = K[5];
        float g = K[6], h  = K[7], i = K[8];
        float A  = e * i - f * h;
        float Bv = -(d * i - f * g);
        float Cv = d * h - e * g;
        float id = 1.0f / (a * A + bb * Bv + c * Cv);
        float inv[9];
        inv[0] = A * id;  inv[1] = (c * h - bb * i) * id; inv[2] = (bb * f - c * e) * id;
        inv[3] = Bv * id; inv[4] = (a * i - c * g) * id;  inv[5] = (c * d - a * f) * id;
        inv[6] = Cv * id; inv[7] = (bb * g - a * h) * id; inv[8] = (a * e - bb * d) * id;
        #pragma unroll
        for (int r = 0; r < 3; r++)
            #pragma unroll
            for (int col = 0; col < 3; col++)
                comb[r * 3 + col] = R[r * 3 + 0] * inv[0 + col]
                                  + R[r * 3 + 1] * inv[3 + col]
                                  + R[r * 3 + 2] * inv[6 + col];
        tr[0] = trans[cam * 3 + 0];
        tr[1] = trans[cam * 3 + 1];
        tr[2] = trans[cam * 3 + 2];
    }

    // --- phase 1: feat = W @ x, FFMA2 over M-pairs (16 outputs/thread) ---
    ull acc[4][2];
    #pragma unroll
    for (int i4 = 0; i4 < 4; i4++)
        #pragma unroll
        for (int j = 0; j < 2; j++) acc[i4][j] = 0ull;

    const float* xcam = x + (size_t)cam * CAM_C * HW;

    for (int kc = 0; kc < CAM_C; kc += BK) {
        // W chunk: lanes take consecutive m (conflict-free smem store;
        // gmem lines (m, k-block) are L1-reused across the kk warps)
        #pragma unroll
        for (int it = 0; it < (BM * BK) / NTHREADS; it++) {
            int idx = it * NTHREADS + tid;
            int kk  = idx >> 7;           // 0..31
            int m   = idx & 127;          // consecutive per lane
            Ws[kk * WS_STRIDE + m] = (m < M_FEAT) ? depth_w[m * CAM_C + kc + kk] : 0.f;
        }
        // X chunk: coalesced both sides
        #pragma unroll
        for (int it = 0; it < (BK * BN) / NTHREADS; it++) {
            int idx = it * NTHREADS + tid;
            int kk  = idx >> 6;
            int np  = idx & 63;
            Xs[kk * XS_STRIDE + np] = xcam[(size_t)(kc + kk) * HW + p0 + np];
        }
        __syncthreads();

        #pragma unroll 4
        for (int kk = 0; kk < BK; kk++) {
            ull wp[4];
            #pragma unroll
            for (int i4 = 0; i4 < 4; i4++)    // warp-broadcast LDS.64
                wp[i4] = *(const ull*)&Ws[kk * WS_STRIDE + tm * 8 + 2 * i4];
            ull xv2 = *(const ull*)&Xs[kk * XS_STRIDE + tn * 2];   // LDS.64, 2 pixels
            float x0, x1;
            asm("mov.b64 {%0, %1}, %2;" : "=f"(x0), "=f"(x1) : "l"(xv2));
            ull xd[2];
            asm("mov.b64 %0, {%1, %1};" : "=l"(xd[0]) : "f"(x0));
            asm("mov.b64 %0, {%1, %1};" : "=l"(xd[1]) : "f"(x1));
            #pragma unroll
            for (int i4 = 0; i4 < 4; i4++)
                #pragma unroll
                for (int j = 0; j < 2; j++)
                    asm("fma.rn.f32x2 %0, %1, %2, %0;"
                        : "+l"(acc[i4][j]) : "l"(wp[i4]), "l"(xd[j]));
        }
        __syncthreads();
    }

    // --- phase 2: unpack accs (+bias) into depthS / ctxS ---
    float* depthS = smem;                     // [pix][61]
    float* ctxS   = smem + BN * DS_STRIDE;    // [pix][68]

    #pragma unroll
    for (int i4 = 0; i4 < 4; i4++) {
        int m0 = tm * 8 + 2 * i4;
        float b0 = (m0     < M_FEAT) ? depth_b[m0]     : 0.f;
        float b1 = (m0 + 1 < M_FEAT) ? depth_b[m0 + 1] : 0.f;
        #pragma unroll
        for (int j = 0; j < 2; j++) {
            float lo, hi;
            asm("mov.b64 {%0, %1}, %2;" : "=f"(lo), "=f"(hi) : "l"(acc[i4][j]));
            int pix = tn * 2 + j;
            float v0 = lo + b0, v1 = hi + b1;
            if (m0 < D_BINS)       depthS[pix * DS_STRIDE + m0] = v0;
            else if (m0 < M_FEAT)  ctxS[pix * CS_STRIDE + (m0 - D_BINS)] = v0;
            int m1 = m0 + 1;
            if (m1 < D_BINS)       depthS[pix * DS_STRIDE + m1] = v1;
            else if (m1 < M_FEAT)  ctxS[pix * CS_STRIDE + (m1 - D_BINS)] = v1;
        }
    }
    __syncthreads();

    // --- softmax over depth bins, one thread per pixel ---
    if (tid < BN) {
        float* row = depthS + tid * DS_STRIDE;
        float mx = -1e30f;
        #pragma unroll 4
        for (int d = 0; d < D_BINS; d++) mx = fmaxf(mx, row[d]);
        float s = 0.f;
        #pragma unroll 4
        for (int d = 0; d < D_BINS; d++) {
            float e = __expf(row[d] - mx);
            row[d] = e;
            s += e;
        }
        float invs = 1.0f / s;
        #pragma unroll 4
        for (int d = 0; d < D_BINS; d++) row[d] *= invs;
    }
    __syncthreads();

    // --- scatter: flat loop, 16x red.v4 per valid point ---
    const float c00 = comb[0], c01 = comb[1], c02 = comb[2];
    const float c10 = comb[3], c11 = comb[4], c12 = comb[5];
    const float c20 = comb[6], c21 = comb[7], c22 = comb[8];
    const float t0 = tr[0], t1 = tr[1], t2 = tr[2];
    const float xstep = 703.0f / 43.0f;
    const float ystep = 255.0f / 15.0f;

    float* base = g_scratch + (size_t)b * NCELL * OUT_C;

    for (int idx = tid; idx < BN * D_BINS; idx += NTHREADS) {
        int pix = idx / D_BINS;
        int d   = idx - pix * D_BINS;
        int hw  = p0 + pix;
        int h   = hw / FW;
        int w   = hw - h * FW;

        float ds  = 1.0f + (float)d;
        float xim = (float)w * xstep;
        float yim = (float)h * ystep;
        float px = xim * ds, py = yim * ds, pz = ds;

        float gx = c00 * px + c01 * py + c02 * pz + t0;
        float gy = c10 * px + c11 * py + c12 * pz + t1;
        float gz = c20 * px + c21 * py + c22 * pz + t2;

        int cx = (int)floorf((gx + 51.2f) / 0.8f);
        int cy = (int)floorf((gy + 51.2f) / 0.8f);
        int cz = (int)floorf((gz + 10.0f) / 20.0f);

        if (((unsigned)cx < (unsigned)NX) && ((unsigned)cy < (unsigned)NY) && cz == 0) {
            float dwgt = depthS[pix * DS_STRIDE + d];
            float* dst = base + ((size_t)cy * NX + cx) * OUT_C;
            const float4* cv = (const float4*)(ctxS + pix * CS_STRIDE);
            #pragma unroll
            for (int c4 = 0; c4 < OUT_C / 4; c4++) {
                float4 v = cv[c4];
                asm volatile(
                    "red.global.add.v4.f32 [%0], {%1, %2, %3, %4};"
                    :: "l"(dst + c4 * 4),
                       "f"(v.x * dwgt), "f"(v.y * dwgt), "f"(v.z * dwgt), "f"(v.w * dwgt)
                    : "memory");
            }
        }
    }
}

// -------- transpose (B, cell, C) -> (B, C, cell), READ-ONLY --------
__global__ void transpose_bev_kernel(float* __restrict__ out)
{
    __shared__ float tile[32][33];
    int bz    = blockIdx.z;                 // batch
    int c0    = blockIdx.y * 32;            // channel tile
    int cell0 = blockIdx.x * 32;            // cell tile
    int tx = threadIdx.x, ty = threadIdx.y; // 32 x 8

    #pragma unroll
    for (int i = ty; i < 32; i += 8)
        tile[i][tx] = g_scratch[((size_t)bz * NCELL + cell0 + i) * OUT_C + c0 + tx];
    __syncthreads();
    #pragma unroll
    for (int i = ty; i < 32; i += 8)
        out[((size_t)(bz * OUT_C + c0 + i)) * NCELL + cell0 + tx] = tile[tx][i];
}

// ---------------- launch ----------------
extern "C" void kernel_launch(void* const* d_in, const int* in_sizes, int n_in,
                              void* d_out, int out_size)
{
    const float* x       = (const float*)d_in[0];
    const float* rots    = (const float*)d_in[1];
    const float* trans   = (const float*)d_in[2];
    const float* intrins = (const float*)d_in[3];
    const float* depth_w = (const float*)d_in[4];
    const float* depth_b = (const float*)d_in[5];
    float* out = (float*)d_out;

    // zero scratch first (plain stores on clean lines, before any reds)
    {
        size_t n4 = (size_t)SCR_SZ / 4;   // 524288 float4
        zero_scratch_kernel<<<(unsigned)(n4 / 256), 256>>>();
    }

    // fused GEMM + softmax + scatter: one block per (camera, 64-pixel tile)
    {
        dim3 grid(HW / BN, CAMS);   // (11, 12)
        lss_fused_kernel<<<grid, NTHREADS>>>(x, rots, trans, intrins, depth_w, depth_b);
    }

    // transpose scratch into output layout (B, OUT_C, NY, NX) — read-only
    {
        dim3 grid(NCELL / 32, OUT_C / 32, B_);   // (512, 2, 2)
        transpose_bev_kernel<<<grid, dim3(32, 8)>>>(out);
    }
    (void)in_sizes; (void)n_in; (void)out_size;
}

// round 6
// speedup vs baseline: 2.4536x; 2.1701x over previous
#include <cuda_runtime.h>
#include <math.h>

// ---------------- problem constants (fixed shapes) ----------------
#define B_      2
#define N_      6
#define CAMS    (B_ * N_)          // 12
#define CAM_C   256
#define OUT_C   64
#define D_BINS  59
#define M_FEAT  (D_BINS + OUT_C)   // 123
#define FH      16
#define FW      44
#define HW      (FH * FW)          // 704
#define NX      128
#define NY      128
#define NCELL   (NX * NY)          // 16384 (NZ = 1)

// tile: 4 image columns x 16 rows = 64 pixels. np = wl*16 + h
#define WCOLS   4
#define BM 128
#define BN 64
#define BK 32
#define NTHREADS 512

#define WS_STRIDE 130   // even -> aligned LDS.64 rows (2-way store conflict only)
#define XS_STRIDE 68
#define DS_STRIDE 61    // depthS per-pixel row (odd -> conflict-free)
#define CS_STRIDE 68    // ctxS per-pixel row (16B multiple -> aligned float4)

#define SCR_SZ (B_ * NCELL * OUT_C)   // 2M floats = 8 MB

typedef unsigned long long ull;

// scratch BEV accumulator, channel-contiguous: (B, cell, OUT_C).
// Zeroed by zero_scratch_kernel at the head of every launch/replay.
__device__ float g_scratch[SCR_SZ];

// ---------------- zero scratch (clean lines BEFORE the reds) -------
__global__ void zero_scratch_kernel() {
    size_t i = (size_t)blockIdx.x * blockDim.x + threadIdx.x;
    ((float4*)g_scratch)[i] = make_float4(0.f, 0.f, 0.f, 0.f);
}

// ---------------- fused GEMM + softmax + column-combined scatter ----------
__global__ __launch_bounds__(NTHREADS, 1)
void lss_fused_kernel(const float* __restrict__ x,
                      const float* __restrict__ rots,
                      const float* __restrict__ trans,
                      const float* __restrict__ intrins,
                      const float* __restrict__ depth_w,
                      const float* __restrict__ depth_b)
{
    // phase 1: Ws[32][130] + Xs[32][68] = 6336 floats
    // phase 2: depthS[64][61] + ctxS[64][68] = 8256 floats (33 KB)
    __shared__ __align__(16) float smem[BN * DS_STRIDE + BN * CS_STRIDE];
    __shared__ float comb[9];
    __shared__ float tr[3];
    __shared__ int   s_fast;

    float* Ws = smem;                       // [kk][m]
    float* Xs = smem + BK * WS_STRIDE;      // [kk][np]

    const int cam = blockIdx.y;             // 0..11
    const int b   = cam / N_;
    const int w0  = blockIdx.x * WCOLS;     // image-column group start
    const int tid = threadIdx.x;
    const int tm  = tid >> 5;               // warp 0..15 -> 8 M-rows (4 pairs)
    const int tn  = tid & 31;               // 0..31 -> 2 pixels

    // --- geometry setup: comb = rots @ inv(K) (thread 0) ---
    if (tid == 0) {
        const float* R = rots    + cam * 9;
        const float* K = intrins + cam * 9;
        float a = K[0], bb = K[1], c = K[2];
        float d = K[3], e  = K[4], f = K[5];
        float g = K[6], h  = K[7], i = K[8];
        float A  = e * i - f * h;
        float Bv = -(d * i - f * g);
        float Cv = d * h - e * g;
        float id = 1.0f / (a * A + bb * Bv + c * Cv);
        float inv[9];
        inv[0] = A * id;  inv[1] = (c * h - bb * i) * id; inv[2] = (bb * f - c * e) * id;
        inv[3] = Bv * id; inv[4] = (a * i - c * g) * id;  inv[5] = (c * d - a * f) * id;
        inv[6] = Cv * id; inv[7] = (bb * g - a * h) * id; inv[8] = (a * e - bb * d) * id;
        #pragma unroll
        for (int r = 0; r < 3; r++)
            #pragma unroll
            for (int col = 0; col < 3; col++)
                comb[r * 3 + col] = R[r * 3 + 0] * inv[0 + col]
                                  + R[r * 3 + 1] * inv[3 + col]
                                  + R[r * 3 + 2] * inv[6 + col];
        tr[0] = trans[cam * 3 + 0];
        tr[1] = trans[cam * 3 + 1];
        tr[2] = trans[cam * 3 + 2];
        // fast path: gx, gy independent of image row (exact zeros)
        s_fast = (comb[1] == 0.0f) && (comb[4] == 0.0f);
    }

    // --- phase 1: feat = W @ x, FFMA2 over M-pairs ---
    ull acc[4][2];
    #pragma unroll
    for (int i4 = 0; i4 < 4; i4++)
        #pragma unroll
        for (int j = 0; j < 2; j++) acc[i4][j] = 0ull;

    const float* xcam = x + (size_t)cam * CAM_C * HW;

    for (int kc = 0; kc < CAM_C; kc += BK) {
        // W chunk: lane-consecutive kk -> coalesced 128B global reads
        #pragma unroll
        for (int it = 0; it < (BM * BK) / NTHREADS; it++) {
            int idx = it * NTHREADS + tid;
            int m   = idx >> 5;
            int kk  = idx & 31;
            Ws[kk * WS_STRIDE + m] = (m < M_FEAT) ? depth_w[m * CAM_C + kc + kk] : 0.f;
        }
        // X chunk: pixel np = wl*16 + h, gmem addr = ch*HW + h*FW + w0 + wl
        #pragma unroll
        for (int it = 0; it < (BK * BN) / NTHREADS; it++) {
            int idx = it * NTHREADS + tid;
            int kk  = idx >> 6;
            int sub = idx & 63;
            int wl  = sub & 3;
            int h   = sub >> 2;
            Xs[kk * XS_STRIDE + wl * 16 + h] =
                xcam[(size_t)(kc + kk) * HW + h * FW + w0 + wl];
        }
        __syncthreads();

        #pragma unroll 4
        for (int kk = 0; kk < BK; kk++) {
            ull wp[4];
            #pragma unroll
            for (int i4 = 0; i4 < 4; i4++)      // warp-broadcast LDS.64
                wp[i4] = *(const ull*)&Ws[kk * WS_STRIDE + tm * 8 + 2 * i4];
            ull xv2 = *(const ull*)&Xs[kk * XS_STRIDE + tn * 2];
            float x0, x1;
            asm("mov.b64 {%0, %1}, %2;" : "=f"(x0), "=f"(x1) : "l"(xv2));
            ull xd[2];
            asm("mov.b64 %0, {%1, %1};" : "=l"(xd[0]) : "f"(x0));
            asm("mov.b64 %0, {%1, %1};" : "=l"(xd[1]) : "f"(x1));
            #pragma unroll
            for (int i4 = 0; i4 < 4; i4++)
                #pragma unroll
                for (int j = 0; j < 2; j++)
                    asm("fma.rn.f32x2 %0, %1, %2, %0;"
                        : "+l"(acc[i4][j]) : "l"(wp[i4]), "l"(xd[j]));
        }
        __syncthreads();
    }

    // --- phase 2: unpack accs (+bias) into depthS / ctxS ---
    float* depthS = smem;                     // [np][61]
    float* ctxS   = smem + BN * DS_STRIDE;    // [np][68]

    #pragma unroll
    for (int i4 = 0; i4 < 4; i4++) {
        int m0 = tm * 8 + 2 * i4;
        float b0 = (m0     < M_FEAT) ? depth_b[m0]     : 0.f;
        float b1 = (m0 + 1 < M_FEAT) ? depth_b[m0 + 1] : 0.f;
        #pragma unroll
        for (int j = 0; j < 2; j++) {
            float lo, hi;
            asm("mov.b64 {%0, %1}, %2;" : "=f"(lo), "=f"(hi) : "l"(acc[i4][j]));
            int pix = tn * 2 + j;
            float v0 = lo + b0, v1 = hi + b1;
            if (m0 < D_BINS)       depthS[pix * DS_STRIDE + m0] = v0;
            else if (m0 < M_FEAT)  ctxS[pix * CS_STRIDE + (m0 - D_BINS)] = v0;
            int m1 = m0 + 1;
            if (m1 < D_BINS)       depthS[pix * DS_STRIDE + m1] = v1;
            else if (m1 < M_FEAT)  ctxS[pix * CS_STRIDE + (m1 - D_BINS)] = v1;
        }
    }
    __syncthreads();

    const float c00 = comb[0], c01 = comb[1], c02 = comb[2];
    const float c10 = comb[3], c11 = comb[4], c12 = comb[5];
    const float c20 = comb[6], c21 = comb[7], c22 = comb[8];
    const float t0 = tr[0], t1 = tr[1], t2 = tr[2];
    const float xstep = 703.0f / 43.0f;
    const float ystep = 255.0f / 15.0f;
    const int   fast  = s_fast;

    // --- softmax per pixel; in fast path also zero z-invalid bins ---
    if (tid < BN) {
        float* row = depthS + tid * DS_STRIDE;
        float mx = -1e30f;
        #pragma unroll 4
        for (int d = 0; d < D_BINS; d++) mx = fmaxf(mx, row[d]);
        float s = 0.f;
        #pragma unroll 4
        for (int d = 0; d < D_BINS; d++) {
            float e = __expf(row[d] - mx);
            row[d] = e;
            s += e;
        }
        float invs = 1.0f / s;
        #pragma unroll 4
        for (int d = 0; d < D_BINS; d++) row[d] *= invs;

        if (fast) {
            int wl = tid >> 4, h = tid & 15;
            float xim = (float)(w0 + wl) * xstep;
            float yim = (float)h * ystep;
            for (int d = 0; d < D_BINS; d++) {
                float ds = 1.0f + (float)d;
                float gz = c20 * (xim * ds) + c21 * (yim * ds) + c22 * ds + t2;
                int cz = (int)floorf((gz + 10.0f) / 20.0f);
                if (cz != 0) row[d] = 0.f;
            }
        }
    }
    __syncthreads();

    float* base = g_scratch + (size_t)b * NCELL * OUT_C;

    if (fast) {
        // --- fast scatter: one task per (column, depth); combine 16 rows ---
        const int hw16 = tid >> 4;   // half-warp id 0..31
        const int l    = tid & 15;   // lane in half-warp -> channels 4l..4l+3
        for (int t = hw16; t < WCOLS * D_BINS; t += 32) {
            int wl = t / D_BINS;
            int d  = t - wl * D_BINS;
            float ds  = 1.0f + (float)d;
            float xim = (float)(w0 + wl) * xstep;
            float px = xim * ds, pz = ds;
            float gx = c00 * px + c02 * pz + t0;   // c01 term is exactly 0
            float gy = c10 * px + c12 * pz + t1;   // c11 term is exactly 0
            int cx = (int)floorf((gx + 51.2f) / 0.8f);
            int cy = (int)floorf((gy + 51.2f) / 0.8f);
            if (((unsigned)cx >= (unsigned)NX) || ((unsigned)cy >= (unsigned)NY))
                continue;

            const float* dcol = depthS + (wl * 16) * DS_STRIDE + d;
            const float* crow = ctxS   + (wl * 16) * CS_STRIDE + l * 4;
            float4 v = make_float4(0.f, 0.f, 0.f, 0.f);
            float dwsum = 0.f;
            #pragma unroll
            for (int h = 0; h < 16; h++) {
                float dw = dcol[h * DS_STRIDE];          // broadcast LDS
                dwsum += dw;
                float4 cc = *(const float4*)(crow + h * CS_STRIDE);
                v.x += dw * cc.x; v.y += dw * cc.y;
                v.z += dw * cc.z; v.w += dw * cc.w;
            }
            if (dwsum != 0.f) {
                float* dst = base + ((size_t)cy * NX + cx) * OUT_C + l * 4;
                asm volatile("red.global.add.v4.f32 [%0], {%1, %2, %3, %4};"
                             :: "l"(dst), "f"(v.x), "f"(v.y), "f"(v.z), "f"(v.w)
                             : "memory");
            }
        }
    } else {
        // --- generic fallback: per-point scatter (correct for any geometry) ---
        for (int idx = tid; idx < BN * D_BINS; idx += NTHREADS) {
            int np = idx / D_BINS;
            int d  = idx - np * D_BINS;
            int wl = np >> 4, h = np & 15;
            float ds  = 1.0f + (float)d;
            float xim = (float)(w0 + wl) * xstep;
            float yim = (float)h * ystep;
            float px = xim * ds, py = yim * ds, pz = ds;
            float gx = c00 * px + c01 * py + c02 * pz + t0;
            float gy = c10 * px + c11 * py + c12 * pz + t1;
            float gz = c20 * px + c21 * py + c22 * pz + t2;
            int cx = (int)floorf((gx + 51.2f) / 0.8f);
            int cy = (int)floorf((gy + 51.2f) / 0.8f);
            int cz = (int)floorf((gz + 10.0f) / 20.0f);
            if (((unsigned)cx < (unsigned)NX) && ((unsigned)cy < (unsigned)NY) && cz == 0) {
                float dwgt = depthS[np * DS_STRIDE + d];
                float* dst = base + ((size_t)cy * NX + cx) * OUT_C;
                const float4* cv = (const float4*)(ctxS + np * CS_STRIDE);
                #pragma unroll
                for (int c4 = 0; c4 < OUT_C / 4; c4++) {
                    float4 v = cv[c4];
                    asm volatile("red.global.add.v4.f32 [%0], {%1, %2, %3, %4};"
                                 :: "l"(dst + c4 * 4),
                                    "f"(v.x * dwgt), "f"(v.y * dwgt),
                                    "f"(v.z * dwgt), "f"(v.w * dwgt) : "memory");
                }
            }
        }
    }
}

// -------- transpose (B, cell, C) -> (B, C, cell), READ-ONLY --------
__global__ void transpose_bev_kernel(float* __restrict__ out)
{
    __shared__ float tile[32][33];
    int bz    = blockIdx.z;
    int c0    = blockIdx.y * 32;
    int cell0 = blockIdx.x * 32;
    int tx = threadIdx.x, ty = threadIdx.y;   // 32 x 8

    #pragma unroll
    for (int i = ty; i < 32; i += 8)
        tile[i][tx] = g_scratch[((size_t)bz * NCELL + cell0 + i) * OUT_C + c0 + tx];
    __syncthreads();
    #pragma unroll
    for (int i = ty; i < 32; i += 8)
        out[((size_t)(bz * OUT_C + c0 + i)) * NCELL + cell0 + tx] = tile[tx][i];
}

// ---------------- launch ----------------
extern "C" void kernel_launch(void* const* d_in, const int* in_sizes, int n_in,
                              void* d_out, int out_size)
{
    const float* x       = (const float*)d_in[0];
    const float* rots    = (const float*)d_in[1];
    const float* trans   = (const float*)d_in[2];
    const float* intrins = (const float*)d_in[3];
    const float* depth_w = (const float*)d_in[4];
    const float* depth_b = (const float*)d_in[5];
    float* out = (float*)d_out;

    // zero scratch first (plain stores on clean lines, before any reds)
    {
        size_t n4 = (size_t)SCR_SZ / 4;
        zero_scratch_kernel<<<(unsigned)(n4 / 256), 256>>>();
    }

    // fused GEMM + softmax + scatter: block per (camera, 4-column group)
    {
        dim3 grid(FW / WCOLS, CAMS);   // (11, 12)
        lss_fused_kernel<<<grid, NTHREADS>>>(x, rots, trans, intrins, depth_w, depth_b);
    }

    // transpose scratch into output layout (B, OUT_C, NY, NX) — read-only
    {
        dim3 grid(NCELL / 32, OUT_C / 32, B_);   // (512, 2, 2)
        transpose_bev_kernel<<<grid, dim3(32, 8)>>>(out);
    }
    (void)in_sizes; (void)n_in; (void)out_size;
}

// round 7
// speedup vs baseline: 2.4590x; 1.0022x over previous
#include <cuda_runtime.h>
#include <math.h>

// ---------------- problem constants (fixed shapes) ----------------
#define B_      2
#define N_      6
#define CAMS    (B_ * N_)          // 12
#define CAM_C   256
#define OUT_C   64
#define D_BINS  59
#define M_FEAT  (D_BINS + OUT_C)   // 123
#define FH      16
#define FW      44
#define HW      (FH * FW)          // 704
#define NX      128
#define NY      128
#define NCELL   (NX * NY)          // 16384 (NZ = 1)

// tile: 4 image columns x 16 rows = 64 pixels. np = wl*16 + h
#define WCOLS   4
#define BM 128
#define BN 64
#define BK 32
#define NTHREADS 512
#define NBLOCKS  ((FW / WCOLS) * CAMS)   // 132 (<= 148 SMs: all resident, wave 1)

#define WS_STRIDE 130
#define XS_STRIDE 68
#define DS_STRIDE 61
#define CS_STRIDE 68

#define SCR_SZ (B_ * NCELL * OUT_C)   // 2M floats = 8 MB

typedef unsigned long long ull;

// scratch BEV accumulator, channel-contiguous: (B, cell, OUT_C).
// Zeroed cooperatively at the head of the fused kernel (grid barrier below).
__device__ float g_scratch[SCR_SZ];
// zero-phase completion counter; reset to 0 by transpose kernel each launch.
__device__ int g_cnt;

// ---------------- fused zero + GEMM + softmax + column-combined scatter ----
__global__ __launch_bounds__(NTHREADS, 1)
void lss_fused_kernel(const float* __restrict__ x,
                      const float* __restrict__ rots,
                      const float* __restrict__ trans,
                      const float* __restrict__ intrins,
                      const float* __restrict__ depth_w,
                      const float* __restrict__ depth_b)
{
    __shared__ __align__(16) float smem[BN * DS_STRIDE + BN * CS_STRIDE];
    __shared__ float comb[9];
    __shared__ float tr[3];
    __shared__ int   s_fast;

    float* Ws = smem;                       // [kk][m]
    float* Xs = smem + BK * WS_STRIDE;      // [kk][np]

    const int cam = blockIdx.y;             // 0..11
    const int b   = cam / N_;
    const int w0  = blockIdx.x * WCOLS;     // image-column group start
    const int tid = threadIdx.x;
    const int tm  = tid >> 5;               // warp 0..15 -> 8 M-rows (4 pairs)
    const int tn  = tid & 31;               // 0..31 -> 2 pixels

    // --- zero this block's slice of scratch, then signal ---
    {
        const int n4 = SCR_SZ / 4;                         // 524288 float4
        const int bid = blockIdx.y * gridDim.x + blockIdx.x;
        const int chunk = (n4 + NBLOCKS - 1) / NBLOCKS;    // 3972
        int s = bid * chunk;
        int e = s + chunk; if (e > n4) e = n4;
        float4* p = (float4*)g_scratch;
        for (int i = s + tid; i < e; i += NTHREADS)
            p[i] = make_float4(0.f, 0.f, 0.f, 0.f);
        __threadfence();
        if (tid == 0) atomicAdd(&g_cnt, 1);
    }

    // --- geometry setup: comb = rots @ inv(K) (thread 0) ---
    if (tid == 0) {
        const float* R = rots    + cam * 9;
        const float* K = intrins + cam * 9;
        float a = K[0], bb = K[1], c = K[2];
        float d = K[3], e  = K[4], f = K[5];
        float g = K[6], h  = K[7], i = K[8];
        float A  = e * i - f * h;
        float Bv = -(d * i - f * g);
        float Cv = d * h - e * g;
        float id = 1.0f / (a * A + bb * Bv + c * Cv);
        float inv[9];
        inv[0] = A * id;  inv[1] = (c * h - bb * i) * id; inv[2] = (bb * f - c * e) * id;
        inv[3] = Bv * id; inv[4] = (a * i - c * g) * id;  inv[5] = (c * d - a * f) * id;
        inv[6] = Cv * id; inv[7] = (bb * g - a * h) * id; inv[8] = (a * e - bb * d) * id;
        #pragma unroll
        for (int r = 0; r < 3; r++)
            #pragma unroll
            for (int col = 0; col < 3; col++)
                comb[r * 3 + col] = R[r * 3 + 0] * inv[0 + col]
                                  + R[r * 3 + 1] * inv[3 + col]
                                  + R[r * 3 + 2] * inv[6 + col];
        tr[0] = trans[cam * 3 + 0];
        tr[1] = trans[cam * 3 + 1];
        tr[2] = trans[cam * 3 + 2];
        // fast path: gx, gy independent of image row (exact zeros)
        s_fast = (comb[1] == 0.0f) && (comb[4] == 0.0f);
    }

    // --- phase 1: feat = W @ x, FFMA2 over M-pairs ---
    ull acc[4][2];
    #pragma unroll
    for (int i4 = 0; i4 < 4; i4++)
        #pragma unroll
        for (int j = 0; j < 2; j++) acc[i4][j] = 0ull;

    const float* xcam = x + (size_t)cam * CAM_C * HW;

    for (int kc = 0; kc < CAM_C; kc += BK) {
        // W chunk: lane-consecutive kk -> coalesced 128B global reads
        #pragma unroll
        for (int it = 0; it < (BM * BK) / NTHREADS; it++) {
            int idx = it * NTHREADS + tid;
            int m   = idx >> 5;
            int kk  = idx & 31;
            Ws[kk * WS_STRIDE + m] = (m < M_FEAT) ? depth_w[m * CAM_C + kc + kk] : 0.f;
        }
        // X chunk: pixel np = wl*16 + h, gmem addr = ch*HW + h*FW + w0 + wl
        #pragma unroll
        for (int it = 0; it < (BK * BN) / NTHREADS; it++) {
            int idx = it * NTHREADS + tid;
            int kk  = idx >> 6;
            int sub = idx & 63;
            int wl  = sub & 3;
            int h   = sub >> 2;
            Xs[kk * XS_STRIDE + wl * 16 + h] =
                xcam[(size_t)(kc + kk) * HW + h * FW + w0 + wl];
        }
        __syncthreads();

        #pragma unroll 4
        for (int kk = 0; kk < BK; kk++) {
            ull wp[4];
            #pragma unroll
            for (int i4 = 0; i4 < 4; i4++)      // warp-broadcast LDS.64
                wp[i4] = *(const ull*)&Ws[kk * WS_STRIDE + tm * 8 + 2 * i4];
            ull xv2 = *(const ull*)&Xs[kk * XS_STRIDE + tn * 2];
            float x0, x1;
            asm("mov.b64 {%0, %1}, %2;" : "=f"(x0), "=f"(x1) : "l"(xv2));
            ull xd[2];
            asm("mov.b64 %0, {%1, %1};" : "=l"(xd[0]) : "f"(x0));
            asm("mov.b64 %0, {%1, %1};" : "=l"(xd[1]) : "f"(x1));
            #pragma unroll
            for (int i4 = 0; i4 < 4; i4++)
                #pragma unroll
                for (int j = 0; j < 2; j++)
                    asm("fma.rn.f32x2 %0, %1, %2, %0;"
                        : "+l"(acc[i4][j]) : "l"(wp[i4]), "l"(xd[j]));
        }
        __syncthreads();
    }

    // --- phase 2: unpack accs (+bias) into depthS / ctxS ---
    float* depthS = smem;                     // [np][61]
    float* ctxS   = smem + BN * DS_STRIDE;    // [np][68]

    #pragma unroll
    for (int i4 = 0; i4 < 4; i4++) {
        int m0 = tm * 8 + 2 * i4;
        float b0 = (m0     < M_FEAT) ? depth_b[m0]     : 0.f;
        float b1 = (m0 + 1 < M_FEAT) ? depth_b[m0 + 1] : 0.f;
        #pragma unroll
        for (int j = 0; j < 2; j++) {
            float lo, hi;
            asm("mov.b64 {%0, %1}, %2;" : "=f"(lo), "=f"(hi) : "l"(acc[i4][j]));
            int pix = tn * 2 + j;
            float v0 = lo + b0, v1 = hi + b1;
            if (m0 < D_BINS)       depthS[pix * DS_STRIDE + m0] = v0;
            else if (m0 < M_FEAT)  ctxS[pix * CS_STRIDE + (m0 - D_BINS)] = v0;
            int m1 = m0 + 1;
            if (m1 < D_BINS)       depthS[pix * DS_STRIDE + m1] = v1;
            else if (m1 < M_FEAT)  ctxS[pix * CS_STRIDE + (m1 - D_BINS)] = v1;
        }
    }
    __syncthreads();

    const float c00 = comb[0], c01 = comb[1], c02 = comb[2];
    const float c10 = comb[3], c11 = comb[4], c12 = comb[5];
    const float c20 = comb[6], c21 = comb[7], c22 = comb[8];
    const float t0 = tr[0], t1 = tr[1], t2 = tr[2];
    const float xstep = 703.0f / 43.0f;
    const float ystep = 255.0f / 15.0f;
    const int   fast  = s_fast;

    // --- softmax per pixel; in fast path also zero z-invalid bins ---
    if (tid < BN) {
        float* row = depthS + tid * DS_STRIDE;
        float mx = -1e30f;
        #pragma unroll 4
        for (int d = 0; d < D_BINS; d++) mx = fmaxf(mx, row[d]);
        float s = 0.f;
        #pragma unroll 4
        for (int d = 0; d < D_BINS; d++) {
            float e = __expf(row[d] - mx);
            row[d] = e;
            s += e;
        }
        float invs = 1.0f / s;
        #pragma unroll 4
        for (int d = 0; d < D_BINS; d++) row[d] *= invs;

        if (fast) {
            int wl = tid >> 4, h = tid & 15;
            float xim = (float)(w0 + wl) * xstep;
            float yim = (float)h * ystep;
            for (int d = 0; d < D_BINS; d++) {
                float ds = 1.0f + (float)d;
                float gz = c20 * (xim * ds) + c21 * (yim * ds) + c22 * ds + t2;
                int cz = (int)floorf((gz + 10.0f) / 20.0f);
                if (cz != 0) row[d] = 0.f;
            }
        }
    }

    // --- grid barrier: all blocks must have finished zeroing scratch.
    // All 132 blocks are co-resident (grid <= SM count), so this cannot
    // deadlock; by now (post-GEMM) the counter is long since full.
    if (tid == 0) {
        while (atomicAdd(&g_cnt, 0) < NBLOCKS) { }
    }
    __syncthreads();   // also publishes softmax results

    float* base = g_scratch + (size_t)b * NCELL * OUT_C;

    if (fast) {
        // --- fast scatter: one task per (column, depth); combine 16 rows ---
        const int hw16 = tid >> 4;   // half-warp id 0..31
        const int l    = tid & 15;   // lane in half-warp -> channels 4l..4l+3
        for (int t = hw16; t < WCOLS * D_BINS; t += 32) {
            int wl = t / D_BINS;
            int d  = t - wl * D_BINS;
            float ds  = 1.0f + (float)d;
            float xim = (float)(w0 + wl) * xstep;
            float px = xim * ds, pz = ds;
            float gx = c00 * px + c02 * pz + t0;   // c01 term is exactly 0
            float gy = c10 * px + c12 * pz + t1;   // c11 term is exactly 0
            int cx = (int)floorf((gx + 51.2f) / 0.8f);
            int cy = (int)floorf((gy + 51.2f) / 0.8f);
            if (((unsigned)cx >= (unsigned)NX) || ((unsigned)cy >= (unsigned)NY))
                continue;

            const float* dcol = depthS + (wl * 16) * DS_STRIDE + d;
            const float* crow = ctxS   + (wl * 16) * CS_STRIDE + l * 4;
            float4 v = make_float4(0.f, 0.f, 0.f, 0.f);
            float dwsum = 0.f;
            #pragma unroll
            for (int h = 0; h < 16; h++) {
                float dw = dcol[h * DS_STRIDE];          // broadcast LDS
                dwsum += dw;
                float4 cc = *(const float4*)(crow + h * CS_STRIDE);
                v.x += dw * cc.x; v.y += dw * cc.y;
                v.z += dw * cc.z; v.w += dw * cc.w;
            }
            if (dwsum != 0.f) {
                float* dst = base + ((size_t)cy * NX + cx) * OUT_C + l * 4;
                asm volatile("red.global.add.v4.f32 [%0], {%1, %2, %3, %4};"
                             :: "l"(dst), "f"(v.x), "f"(v.y), "f"(v.z), "f"(v.w)
                             : "memory");
            }
        }
    } else {
        // --- generic fallback: per-point scatter (correct for any geometry) ---
        for (int idx = tid; idx < BN * D_BINS; idx += NTHREADS) {
            int np = idx / D_BINS;
            int d  = idx - np * D_BINS;
            int wl = np >> 4, h = np & 15;
            float ds  = 1.0f + (float)d;
            float xim = (float)(w0 + wl) * xstep;
            float yim = (float)h * ystep;
            float px = xim * ds, py = yim * ds, pz = ds;
            float gx = c00 * px + c01 * py + c02 * pz + t0;
            float gy = c10 * px + c11 * py + c12 * pz + t1;
            float gz = c20 * px + c21 * py + c22 * pz + t2;
            int cx = (int)floorf((gx + 51.2f) / 0.8f);
            int cy = (int)floorf((gy + 51.2f) / 0.8f);
            int cz = (int)floorf((gz + 10.0f) / 20.0f);
            if (((unsigned)cx < (unsigned)NX) && ((unsigned)cy < (unsigned)NY) && cz == 0) {
                float dwgt = depthS[np * DS_STRIDE + d];
                float* dst = base + ((size_t)cy * NX + cx) * OUT_C;
                const float4* cv = (const float4*)(ctxS + np * CS_STRIDE);
                #pragma unroll
                for (int c4 = 0; c4 < OUT_C / 4; c4++) {
                    float4 v = cv[c4];
                    asm volatile("red.global.add.v4.f32 [%0], {%1, %2, %3, %4};"
                                 :: "l"(dst + c4 * 4),
                                    "f"(v.x * dwgt), "f"(v.y * dwgt),
                                    "f"(v.z * dwgt), "f"(v.w * dwgt) : "memory");
                }
            }
        }
    }
}

// ---- transpose (B, cell, C) -> (B, C, cell), float4 both sides ----
#define TCELLS 64
__global__ void transpose_bev_kernel(float* __restrict__ out)
{
    __shared__ float tile[OUT_C][TCELLS + 1];   // 64 x 65
    const int bz    = blockIdx.y;
    const int cell0 = blockIdx.x * TCELLS;
    const int tid   = threadIdx.x;              // 256

    if (blockIdx.x == 0 && bz == 0 && tid == 0) g_cnt = 0;   // reset barrier

    #pragma unroll
    for (int i = 0; i < 4; i++) {
        int idx  = i * 256 + tid;               // 0..1023
        int cell = idx >> 4;                    // 0..63
        int c4   = idx & 15;
        float4 v = *(const float4*)&g_scratch[
            ((size_t)bz * NCELL + cell0 + cell) * OUT_C + c4 * 4];
        tile[c4 * 4 + 0][cell] = v.x;
        tile[c4 * 4 + 1][cell] = v.y;
        tile[c4 * 4 + 2][cell] = v.z;
        tile[c4 * 4 + 3][cell] = v.w;
    }
    __syncthreads();
    #pragma unroll
    for (int i = 0; i < 4; i++) {
        int idx = i * 256 + tid;
        int ch  = idx >> 4;
        int seg = idx & 15;
        float4 v = make_float4(tile[ch][seg * 4 + 0], tile[ch][seg * 4 + 1],
                               tile[ch][seg * 4 + 2], tile[ch][seg * 4 + 3]);
        *(float4*)&out[((size_t)(bz * OUT_C + ch)) * NCELL + cell0 + seg * 4] = v;
    }
}

// ---------------- launch ----------------
extern "C" void kernel_launch(void* const* d_in, const int* in_sizes, int n_in,
                              void* d_out, int out_size)
{
    const float* x       = (const float*)d_in[0];
    const float* rots    = (const float*)d_in[1];
    const float* trans   = (const float*)d_in[2];
    const float* intrins = (const float*)d_in[3];
    const float* depth_w = (const float*)d_in[4];
    const float* depth_b = (const float*)d_in[5];
    float* out = (float*)d_out;

    // fused zero + GEMM + softmax + scatter: block per (camera, 4-col group)
    {
        dim3 grid(FW / WCOLS, CAMS);   // (11, 12) = 132 blocks
        lss_fused_kernel<<<grid, NTHREADS>>>(x, rots, trans, intrins, depth_w, depth_b);
    }

    // transpose scratch into output layout (B, OUT_C, NY, NX); resets barrier
    {
        dim3 grid(NCELL / TCELLS, B_);   // (256, 2)
        transpose_bev_kernel<<<grid, 256>>>(out);
    }
    (void)in_sizes; (void)n_in; (void)out_size;
}